// round 15
// baseline (speedup 1.0000x reference)
#include <cuda_runtime.h>
#include <cuda_fp16.h>
#include <cstdint>

// Problem constants (fixed by the reference)
#define NN   50000
#define EE   1600000
#define BB   128
#define FXs  16
#define FEs  4
#define FINs 20
#define MMs  64
#define HHs  32
#define MHs  2048   // M*H
#define KK2  48     // reduced K: x(16)|de(4)|x*fac(16,comb w)|rows*fac(4)|cols*fac(4)|0(4)
#define NTILES 391
#define NPAD (NTILES*128)  // 50048

// smem layout for k_mm (dynamic)
// phase 1 (operands): 2 tiles of 128 rows x 112B pitch (96B real = 48 fp16)
#define SM_A  0
#define SM_W  14336
#define TPITCHB 112
// phase 2 (epilogue, reuses same memory): flg@0 (512B), cgs@512 (1KB), buf@2048
#define BUFW 132
#define SMEM_BYTES 69632

// ---------------- scratch (device globals: no allocation allowed) ----------------
__device__ __align__(16) __half2 g_rows16[NN*2];  // fp16x2 atomic accumulators
__device__ __align__(16) __half2 g_cols16[NN*2];
__device__ int   g_winner[NN];
__device__ int   g_cnt[BB];                       // zero-init at load; re-zeroed by k_final
__device__ float g_fact[BB];
__device__ __align__(16) float g_gsum[BB*24];     // per graph: x(16) | de(4) | cols(4)
__device__ __align__(16) float g_W14[40*MHs];     // [f][mh]  f: k1(20) | k4(20), f-major
__device__ __align__(16) __half g_A16[NPAD*KK2];
__device__ __align__(16) __half g_W16[MHs*KK2];   // [mh][k], K-major
__device__ __align__(16) float g_Cg[BB*MHs];      // per-graph offset (+bias_equiv)
__device__ float g_acc[BB*MHs];                   // segsum(relu(...)) accumulator

__device__ __forceinline__ float4 f4s(float4 v, float s) {
    return make_float4(v.x*s, v.y*s, v.z*s, v.w*s);
}
__device__ __forceinline__ uint32_t pkh2(float a, float b) {
    __half2 t = __floats2half2_rn(a, b);
    return *reinterpret_cast<uint32_t*>(&t);
}
__device__ __forceinline__ uint32_t s2u(const void* p) {
    uint32_t a;
    asm("{ .reg .u64 t; cvta.to.shared.u64 t, %1; cvt.u32.u64 %0, t; }" : "=r"(a) : "l"(p));
    return a;
}
__device__ __forceinline__ void redh2(__half2* p, __half2 v) {
    asm volatile("red.global.add.noftz.f16x2 [%0], %1;"
                 :: "l"(p), "r"(*reinterpret_cast<uint32_t*>(&v)) : "memory");
}
__device__ __forceinline__ void red1(float* p, float v) {
    asm volatile("red.global.add.f32 [%0], %1;" :: "l"(p), "f"(v) : "memory");
}
#define LDM4(r, addr) \
    asm volatile("ldmatrix.sync.aligned.m8n8.x4.shared.b16 {%0,%1,%2,%3}, [%4];" \
        : "=r"((r)[0]), "=r"((r)[1]), "=r"((r)[2]), "=r"((r)[3]) : "r"(addr))

__device__ __forceinline__ void mma16816(float* c, const uint32_t* a,
                                         uint32_t b0, uint32_t b1) {
    asm volatile(
        "mma.sync.aligned.m16n8k16.row.col.f32.f16.f16.f32 "
        "{%0,%1,%2,%3}, {%4,%5,%6,%7}, {%8,%9}, {%0,%1,%2,%3};"
        : "+f"(c[0]), "+f"(c[1]), "+f"(c[2]), "+f"(c[3])
        : "r"(a[0]), "r"(a[1]), "r"(a[2]), "r"(a[3]), "r"(b0), "r"(b1));
}

// ---------------- init + weight prep + node-count histogram (fused) ----------------
__global__ void k_init(const float* __restrict__ ke, const int* __restrict__ batch) {
    __shared__ int h[BB];
    int t = threadIdx.x;
    int idx = blockIdx.x * 256 + t;                     // grid covers 262144
    if (t < BB) h[t] = 0;
    __syncthreads();
    if (idx < NN) atomicAdd(&h[batch[idx]], 1);

    if (idx < NN*2) {
        g_rows16[idx] = __floats2half2_rn(0.f, 0.f);
        g_cols16[idx] = __floats2half2_rn(0.f, 0.f);
    }
    if (idx < NN)      g_winner[idx] = -1;
    if (idx < BB*24)   g_gsum[idx] = 0.f;
    if (idx < (NPAD-NN)*KK2)                            // zero A padding rows
        g_A16[NN*KK2 + idx] = __float2half(0.f);
    if (idx < MHs*KK2) {                                // weight prep, single fp16
        int mh = idx / KK2, k = idx % KK2;
        int m = mh >> 5, hh = mh & 31;
        const float* kb = ke + (m*5*HHs + hh)*FINs;
        const int BS = HHs*FINs;
        float v = 0.f;
        if (k < 20)       v = kb[k];                                  // diag
        else if (k < 36)  v = kb[2*BS + (k-20)] + kb[3*BS + (k-20)];  // combined x*fac
        else if (k < 40)  v = kb[2*BS + (k-20)];                      // rows attrs
        else if (k < 44)  v = kb[3*BS + (k-24)];                      // cols attrs
        g_W16[idx] = __float2half_rn(v);
    }
    if (idx < 40*MHs) {                                 // f-major k1|k4 for k_cg
        int f = idx / MHs, mh = idx % MHs;              // consecutive idx -> coalesced
        int m = mh >> 5, hh = mh & 31;
        g_W14[idx] = (f < 20)
            ? ke[((m*5 + 1)*HHs + hh)*FINs + f]
            : ke[((m*5 + 4)*HHs + hh)*FINs + (f - 20)];
    }
    __syncthreads();
    if (t < BB && h[t]) atomicAdd(&g_cnt[t], h[t]);
}

// ---------------- edge scatter (fp16x2 packed atomics) + g_fact from counts --------
__global__ void k_edge(const int* __restrict__ ei, const float* __restrict__ ea) {
    if (blockIdx.x == 0 && threadIdx.x < BB)
        g_fact[threadIdx.x] = 1.0f / (float)g_cnt[threadIdx.x];
    int e = blockIdx.x * 256 + threadIdx.x;
    if (e >= EE) return;
    int s = ei[e], d = ei[EE + e];
    float4 a = ((const float4*)ea)[e];
    __half2 h0 = __floats2half2_rn(a.x, a.y);
    __half2 h1 = __floats2half2_rn(a.z, a.w);
    redh2(g_rows16 + s*2,     h0);
    redh2(g_rows16 + s*2 + 1, h1);
    redh2(g_cols16 + d*2,     h0);
    redh2(g_cols16 + d*2 + 1, h1);
    if (s == d) atomicMax(&g_winner[s], e);
}

// ---------------- per-node basis build (fp16) + shuffle-reduced per-graph sums ------
__global__ void k_node(const float* __restrict__ x, const float* __restrict__ ea,
                       const int* __restrict__ batch) {
    __shared__ float pt[8][24];      // per-warp totals
    __shared__ float ps[8][24];      // per-warp slot1 partials
    int tid = threadIdx.x, lane = tid & 31, warp = tid >> 5;
    int nb = blockIdx.x * 256;
    int n  = nb + tid;
    bool valid = n < NN;
    int g0 = batch[nb];
    int nlast = nb + 255; if (nlast >= NN) nlast = NN - 1;
    int glast = batch[nlast];
    bool two = (glast != g0);

    float4 x0 = {0,0,0,0}, x1 = {0,0,0,0}, x2 = {0,0,0,0}, x3 = {0,0,0,0};
    float4 de = {0,0,0,0}, c = {0,0,0,0};
    int b = g0;
    if (valid) {
        b = batch[n];
        const float4* xr = (const float4*)(x + (size_t)n*FXs);
        x0 = xr[0]; x1 = xr[1]; x2 = xr[2]; x3 = xr[3];
        float2 ca = __half22float2(g_cols16[n*2]);
        float2 cb = __half22float2(g_cols16[n*2 + 1]);
        c = make_float4(ca.x, ca.y, cb.x, cb.y);
        int w = g_winner[n];
        if (w >= 0) de = ((const float4*)ea)[w];
        float fac = g_fact[b];
        float2 rA = __half22float2(g_rows16[n*2]);
        float2 rB = __half22float2(g_rows16[n*2 + 1]);
        float4 r = make_float4(rA.x, rA.y, rB.x, rB.y);
        float4 x0f = f4s(x0,fac), x1f = f4s(x1,fac), x2f = f4s(x2,fac), x3f = f4s(x3,fac);
        float4 rf = f4s(r,fac), cf = f4s(c,fac);
        uint32_t hb[24];
        float4 vals[12] = { x0, x1, x2, x3, de,
                            x0f, x1f, x2f, x3f, rf, cf,
                            make_float4(0.f,0.f,0.f,0.f) };
        #pragma unroll
        for (int i = 0; i < 12; i++) {
            float4 v = vals[i];
            hb[2*i]   = pkh2(v.x, v.y);
            hb[2*i+1] = pkh2(v.z, v.w);
        }
        uint4* dh = (uint4*)(g_A16 + (size_t)n*KK2);
        #pragma unroll
        for (int i = 0; i < 6; i++) dh[i] = ((uint4*)hb)[i];
    }

    // 24 reduced values: x(16) | de(4) | cols(4), plus slot flag
    float v[24] = { x0.x,x0.y,x0.z,x0.w, x1.x,x1.y,x1.z,x1.w,
                    x2.x,x2.y,x2.z,x2.w, x3.x,x3.y,x3.z,x3.w,
                    de.x,de.y,de.z,de.w, c.x,c.y,c.z,c.w };
    float sf = (valid && b != g0) ? 1.f : 0.f;
    #pragma unroll
    for (int i = 0; i < 24; i++) {
        float t = v[i], s1 = t * sf;
        #pragma unroll
        for (int off = 16; off >= 1; off >>= 1) {
            t  += __shfl_xor_sync(0xffffffffu, t,  off);
            s1 += __shfl_xor_sync(0xffffffffu, s1, off);
        }
        if (lane == 0) { pt[warp][i] = t; ps[warp][i] = s1; }
    }
    __syncthreads();
    if (tid < 24) {
        float T = 0.f, S = 0.f;
        #pragma unroll
        for (int w = 0; w < 8; w++) { T += pt[w][tid]; S += ps[w][tid]; }
        red1(&g_gsum[g0*24 + tid], T - S);
        if (two) red1(&g_gsum[glast*24 + tid], S);
    }
}

// ---------------- per-graph offset Cg (+ zero g_acc), f-major coalesced W ----------
// Cg = be + fac*s1 + fac^3*t4
__global__ void k_cg(const float* __restrict__ be) {
    int idx = blockIdx.x * 256 + threadIdx.x;            // BB*MHs = 262144
    if (idx >= BB*MHs) return;
    g_acc[idx] = 0.f;
    int b = idx >> 11;
    int mh = idx & 2047;
    float fac = g_fact[b];
    const float* gs = g_gsum + b*24;
    float s1 = 0.f, t4 = 0.f;
    #pragma unroll
    for (int f = 0; f < 16; f++) {
        s1 += gs[f] * g_W14[f*MHs + mh];
        t4 += gs[f] * g_W14[(20+f)*MHs + mh];
    }
    #pragma unroll
    for (int j = 0; j < 4; j++) {
        s1 += gs[16+j] * g_W14[(16+j)*MHs + mh];   // de part of diag sums
        t4 += gs[20+j] * g_W14[(36+j)*MHs + mh];   // raw cols sums
    }
    g_Cg[idx] = be[mh] + fac*s1 + fac*fac*fac*t4;
}

// ---------------- mma.sync GEMM + ReLU + per-graph reduction (R11 epilogue) --------
// grid (16 mh-tiles, 391 node-tiles), 256 threads (8 warps, 4x2).
// D[128n x 128mh], K=48, single fp16: A16*W16.
__global__ __launch_bounds__(256, 2) void k_mm(const int* __restrict__ batch) {
    extern __shared__ char smem[];
    uint32_t sb = s2u(smem);
    int tid = threadIdx.x;
    int lane = tid & 31, warp = tid >> 5;
    int warpM = warp & 3, warpN = warp >> 2;
    int mb = blockIdx.x * 128, nb = blockIdx.y * 128;

    // ---- load 2 operand tiles into smem (row pitch 112B, 96B real) ----
    {
        int r = tid >> 1, half = tid & 1;
        const uint4* Ah = (const uint4*)(g_A16 + (size_t)(nb + r)*KK2) + half*3;
        const uint4* Wh = (const uint4*)(g_W16 + (size_t)(mb + r)*KK2) + half*3;
        char* base = smem + r*TPITCHB + half*48;
        #pragma unroll
        for (int i = 0; i < 3; i++) {
            *(uint4*)(base + SM_A + i*16) = Ah[i];
            *(uint4*)(base + SM_W + i*16) = Wh[i];
        }
    }
    __syncthreads();

    float c[2][8][4];
    #pragma unroll
    for (int i = 0; i < 2; i++)
        #pragma unroll
        for (int j = 0; j < 8; j++)
            #pragma unroll
            for (int q = 0; q < 4; q++) c[i][j][q] = 0.f;

    // ldmatrix per-lane address components
    int g8 = lane >> 3, l7 = lane & 7;
    int arow = ((g8 & 1) << 3) + l7;           // 0..15
    int aoff = (g8 >> 1) << 4;                 // 0 / 16 bytes
    int brow = ((g8 >> 1) << 3) + l7;
    int boff = (g8 & 1) << 4;
    uint32_t aA = sb + SM_A + (warpM*32 + arow)*TPITCHB + aoff;
    uint32_t bW = sb + SM_W + (warpN*64 + brow)*TPITCHB + boff;

    #pragma unroll
    for (int k = 0; k < 3; k++) {
        int kb = k * 32;                       // 16 k-elems = 32 bytes
        uint32_t a[2][4];
        #pragma unroll
        for (int i = 0; i < 2; i++)
            LDM4(a[i], aA + i*16*TPITCHB + kb);
        #pragma unroll
        for (int jj = 0; jj < 4; jj++) {
            uint32_t bh[4];
            LDM4(bh, bW + jj*16*TPITCHB + kb);
            #pragma unroll
            for (int i = 0; i < 2; i++) {
                mma16816(c[i][jj*2],   a[i], bh[0], bh[1]);
                mma16816(c[i][jj*2+1], a[i], bh[2], bh[3]);
            }
        }
    }
    __syncthreads();   // operand smem dead; reuse for epilogue

    // ---- epilogue: relu(C + Cg) -> buf, per-graph column sums ----
    int g0 = batch[nb];
    int nlast = nb + 127; if (nlast >= NN) nlast = NN - 1;
    int glast = batch[nlast];
    int*   flg = (int*)smem;                   // [128]
    float* cgs = (float*)(smem + 512);         // [2][128]
    float* buf = (float*)(smem + 2048);        // [128][BUFW]
    if (tid < 128) {
        int n = nb + tid;
        flg[tid] = (n < NN && batch[n] != g0) ? 1 : 0;
    } else {
        int t = tid - 128;
        cgs[t]       = g_Cg[(size_t)g0   *MHs + mb + t];
        cgs[128 + t] = g_Cg[(size_t)glast*MHs + mb + t];
    }
    __syncthreads();

    #pragma unroll
    for (int i = 0; i < 2; i++) {
        int ra = warpM*32 + i*16 + (lane >> 2);
        int rb = ra + 8;
        bool va = (nb + ra) < NN, vb = (nb + rb) < NN;
        const float* ca = cgs + flg[ra]*128;
        const float* cb = cgs + flg[rb]*128;
        #pragma unroll
        for (int j = 0; j < 8; j++) {
            int col = warpN*64 + j*8 + (lane & 3)*2;
            float2 v0, v1;
            v0.x = va ? fmaxf(c[i][j][0] + ca[col],   0.f) : 0.f;
            v0.y = va ? fmaxf(c[i][j][1] + ca[col+1], 0.f) : 0.f;
            v1.x = vb ? fmaxf(c[i][j][2] + cb[col],   0.f) : 0.f;
            v1.y = vb ? fmaxf(c[i][j][3] + cb[col+1], 0.f) : 0.f;
            *(float2*)(buf + (size_t)ra*BUFW + col) = v0;
            *(float2*)(buf + (size_t)rb*BUFW + col) = v1;
        }
    }
    __syncthreads();

    {
        int col = tid & 127, half = tid >> 7;
        float s0 = 0.f, s1 = 0.f;
        int r0 = half * 64;
        #pragma unroll 8
        for (int r = r0; r < r0 + 64; r++) {
            float v = buf[(size_t)r*BUFW + col];
            if (flg[r]) s1 += v; else s0 += v;
        }
        atomicAdd(&g_acc[(size_t)g0*MHs + mb + col], s0);
        if (glast != g0) atomicAdd(&g_acc[(size_t)glast*MHs + mb + col], s1);
    }
}

// ---------------- final (+ reset g_cnt for next replay) ----------------
__global__ void k_final(const float* __restrict__ be, const float* __restrict__ kinv,
                        float* __restrict__ out) {
    int b = blockIdx.x;
    int m = threadIdx.x;
    if (m == 0) g_cnt[b] = 0;
    float fac = g_fact[b];
    const float* acc = g_acc + (size_t)b*MHs + m*HHs;
    const float* beh = be + m*HHs;
    const float* kv  = kinv + m*HHs;
    float s = 0.f;
    #pragma unroll
    for (int h = 0; h < HHs; h++)
        s += (acc[h]*fac - fmaxf(beh[h], 0.f)) * kv[h];
    out[b*MMs + m] = s;
}

extern "C" void kernel_launch(void* const* d_in, const int* in_sizes, int n_in,
                              void* d_out, int out_size) {
    const float* x    = (const float*)d_in[0];
    const float* ea   = (const float*)d_in[1];
    const float* ke   = (const float*)d_in[2];
    const float* kinv = (const float*)d_in[3];
    const float* be   = (const float*)d_in[4];
    // d_in[5] = bias_inv: cancels in psi - zerograph
    const int* ei     = (const int*)d_in[6];
    const int* batch  = (const int*)d_in[7];
    float* out = (float*)d_out;

    cudaFuncSetAttribute(k_mm, cudaFuncAttributeMaxDynamicSharedMemorySize, SMEM_BYTES);

    k_init<<<1024, 256>>>(ke, batch);
    k_edge<<<(EE+255)/256, 256>>>(ei, ea);
    k_node<<<(NN+255)/256, 256>>>(x, ea, batch);
    k_cg<<<(BB*MHs)/256, 256>>>(be);
    dim3 gg(MHs/128, NTILES);
    k_mm<<<gg, 256, SMEM_BYTES>>>(batch);
    k_final<<<BB, MMs>>>(be, kinv, out);
}

// round 16
// speedup vs baseline: 1.1159x; 1.1159x over previous
#include <cuda_runtime.h>
#include <cuda_fp16.h>
#include <cstdint>

// Problem constants (fixed by the reference)
#define NN   50000
#define EE   1600000
#define BB   128
#define FXs  16
#define FEs  4
#define FINs 20
#define MMs  64
#define HHs  32
#define MHs  2048   // M*H
#define KK2  48     // reduced K: x(16)|de(4)|x*fac(16,comb w)|rows*fac(4)|cols*fac(4)|0(4)
#define NTILES 391
#define NPAD (NTILES*128)  // 50048

// smem layout for k_mm (dynamic)
// phase 1 (operands): 2 tiles of 128 rows x 112B pitch (96B real = 48 fp16)
#define SM_A  0
#define SM_W  14336
#define TPITCHB 112
// phase 2 (epilogue, reuses same memory): flg@0 (512B), cgs@512 (1KB), buf@2048
#define BUFW 132
#define SMEM_BYTES 69632

// ---------------- scratch (device globals: no allocation allowed) ----------------
__device__ __align__(16) float g_rows[NN*FEs];
__device__ __align__(16) float g_cols[NN*FEs];
__device__ int   g_winner[NN];
__device__ int   g_cnt[BB];                       // zero-init at load; re-zeroed by k_final
__device__ float g_fact[BB];
__device__ __align__(16) float g_gsum[BB*24];     // per graph: x(16) | de(4) | cols(4)
__device__ __align__(16) float g_W14[40*MHs];     // [f][mh]  f: k1(20) | k4(20), f-major
__device__ __align__(16) __half g_A16[NPAD*KK2];
__device__ __align__(16) __half g_W16[MHs*KK2];   // [mh][k], K-major
__device__ __align__(16) float g_Cg[BB*MHs];      // per-graph offset (+bias_equiv)
__device__ float g_acc[BB*MHs];                   // segsum(relu(...)) accumulator

__device__ __forceinline__ float4 f4s(float4 v, float s) {
    return make_float4(v.x*s, v.y*s, v.z*s, v.w*s);
}
__device__ __forceinline__ uint32_t pkh2(float a, float b) {
    __half2 t = __floats2half2_rn(a, b);
    return *reinterpret_cast<uint32_t*>(&t);
}
__device__ __forceinline__ uint32_t s2u(const void* p) {
    uint32_t a;
    asm("{ .reg .u64 t; cvta.to.shared.u64 t, %1; cvt.u32.u64 %0, t; }" : "=r"(a) : "l"(p));
    return a;
}
__device__ __forceinline__ void red4(float* p, float4 v) {
    asm volatile("red.global.add.v4.f32 [%0], {%1, %2, %3, %4};"
                 :: "l"(p), "f"(v.x), "f"(v.y), "f"(v.z), "f"(v.w) : "memory");
}
__device__ __forceinline__ void red1(float* p, float v) {
    asm volatile("red.global.add.f32 [%0], %1;" :: "l"(p), "f"(v) : "memory");
}
#define LDM4(r, addr) \
    asm volatile("ldmatrix.sync.aligned.m8n8.x4.shared.b16 {%0,%1,%2,%3}, [%4];" \
        : "=r"((r)[0]), "=r"((r)[1]), "=r"((r)[2]), "=r"((r)[3]) : "r"(addr))

__device__ __forceinline__ void mma16816(float* c, const uint32_t* a,
                                         uint32_t b0, uint32_t b1) {
    asm volatile(
        "mma.sync.aligned.m16n8k16.row.col.f32.f16.f16.f32 "
        "{%0,%1,%2,%3}, {%4,%5,%6,%7}, {%8,%9}, {%0,%1,%2,%3};"
        : "+f"(c[0]), "+f"(c[1]), "+f"(c[2]), "+f"(c[3])
        : "r"(a[0]), "r"(a[1]), "r"(a[2]), "r"(a[3]), "r"(b0), "r"(b1));
}

// ---------------- init + weight prep + node-count histogram (fused) ----------------
__global__ void k_init(const float* __restrict__ ke, const int* __restrict__ batch) {
    __shared__ int h[BB];
    int t = threadIdx.x;
    int idx = blockIdx.x * 256 + t;                     // grid covers 262144
    if (t < BB) h[t] = 0;
    __syncthreads();
    if (idx < NN) atomicAdd(&h[batch[idx]], 1);

    if (idx < NN*FEs) { g_rows[idx] = 0.f; g_cols[idx] = 0.f; }
    if (idx < NN)      g_winner[idx] = -1;
    if (idx < BB*24)   g_gsum[idx] = 0.f;
    if (idx < (NPAD-NN)*KK2)                            // zero A padding rows
        g_A16[NN*KK2 + idx] = __float2half(0.f);
    if (idx < MHs*KK2) {                                // weight prep, single fp16
        int mh = idx / KK2, k = idx % KK2;
        int m = mh >> 5, hh = mh & 31;
        const float* kb = ke + (m*5*HHs + hh)*FINs;
        const int BS = HHs*FINs;
        float v = 0.f;
        if (k < 20)       v = kb[k];                                  // diag
        else if (k < 36)  v = kb[2*BS + (k-20)] + kb[3*BS + (k-20)];  // combined x*fac
        else if (k < 40)  v = kb[2*BS + (k-20)];                      // rows attrs
        else if (k < 44)  v = kb[3*BS + (k-24)];                      // cols attrs
        g_W16[idx] = __float2half_rn(v);
    }
    if (idx < 40*MHs) {                                 // f-major k1|k4 for k_cg
        int f = idx / MHs, mh = idx % MHs;              // consecutive idx -> coalesced
        int m = mh >> 5, hh = mh & 31;
        g_W14[idx] = (f < 20)
            ? ke[((m*5 + 1)*HHs + hh)*FINs + f]
            : ke[((m*5 + 4)*HHs + hh)*FINs + (f - 20)];
    }
    __syncthreads();
    if (t < BB && h[t]) atomicAdd(&g_cnt[t], h[t]);
}

// ---------------- edge scatter (fp32 red4) + g_fact from counts ----------------
__global__ void k_edge(const int* __restrict__ ei, const float* __restrict__ ea) {
    if (blockIdx.x == 0 && threadIdx.x < BB)
        g_fact[threadIdx.x] = 1.0f / (float)g_cnt[threadIdx.x];
    int e = blockIdx.x * 256 + threadIdx.x;
    if (e >= EE) return;
    int s = ei[e], d = ei[EE + e];
    float4 a = ((const float4*)ea)[e];
    red4(g_rows + s*4, a);
    red4(g_cols + d*4, a);
    if (s == d) atomicMax(&g_winner[s], e);
}

// ---------------- per-node basis build (fp16) + shuffle-reduced per-graph sums ------
__global__ void k_node(const float* __restrict__ x, const float* __restrict__ ea,
                       const int* __restrict__ batch) {
    __shared__ float pt[8][24];      // per-warp totals
    __shared__ float ps[8][24];      // per-warp slot1 partials
    int tid = threadIdx.x, lane = tid & 31, warp = tid >> 5;
    int nb = blockIdx.x * 256;
    int n  = nb + tid;
    bool valid = n < NN;
    int g0 = batch[nb];
    int nlast = nb + 255; if (nlast >= NN) nlast = NN - 1;
    int glast = batch[nlast];
    bool two = (glast != g0);

    float4 x0 = {0,0,0,0}, x1 = {0,0,0,0}, x2 = {0,0,0,0}, x3 = {0,0,0,0};
    float4 de = {0,0,0,0}, c = {0,0,0,0};
    int b = g0;
    if (valid) {
        b = batch[n];
        const float4* xr = (const float4*)(x + (size_t)n*FXs);
        x0 = xr[0]; x1 = xr[1]; x2 = xr[2]; x3 = xr[3];
        c = ((const float4*)g_cols)[n];
        int w = g_winner[n];
        if (w >= 0) de = ((const float4*)ea)[w];
        float fac = g_fact[b];
        float4 r = ((const float4*)g_rows)[n];
        float4 x0f = f4s(x0,fac), x1f = f4s(x1,fac), x2f = f4s(x2,fac), x3f = f4s(x3,fac);
        float4 rf = f4s(r,fac), cf = f4s(c,fac);
        uint32_t hb[24];
        float4 vals[12] = { x0, x1, x2, x3, de,
                            x0f, x1f, x2f, x3f, rf, cf,
                            make_float4(0.f,0.f,0.f,0.f) };
        #pragma unroll
        for (int i = 0; i < 12; i++) {
            float4 v = vals[i];
            hb[2*i]   = pkh2(v.x, v.y);
            hb[2*i+1] = pkh2(v.z, v.w);
        }
        uint4* dh = (uint4*)(g_A16 + (size_t)n*KK2);
        #pragma unroll
        for (int i = 0; i < 6; i++) dh[i] = ((uint4*)hb)[i];
    }

    // 24 reduced values: x(16) | de(4) | cols(4), plus slot flag
    float v[24] = { x0.x,x0.y,x0.z,x0.w, x1.x,x1.y,x1.z,x1.w,
                    x2.x,x2.y,x2.z,x2.w, x3.x,x3.y,x3.z,x3.w,
                    de.x,de.y,de.z,de.w, c.x,c.y,c.z,c.w };
    float sf = (valid && b != g0) ? 1.f : 0.f;
    #pragma unroll
    for (int i = 0; i < 24; i++) {
        float t = v[i], s1 = t * sf;
        #pragma unroll
        for (int off = 16; off >= 1; off >>= 1) {
            t  += __shfl_xor_sync(0xffffffffu, t,  off);
            s1 += __shfl_xor_sync(0xffffffffu, s1, off);
        }
        if (lane == 0) { pt[warp][i] = t; ps[warp][i] = s1; }
    }
    __syncthreads();
    if (tid < 24) {
        float T = 0.f, S = 0.f;
        #pragma unroll
        for (int w = 0; w < 8; w++) { T += pt[w][tid]; S += ps[w][tid]; }
        red1(&g_gsum[g0*24 + tid], T - S);
        if (two) red1(&g_gsum[glast*24 + tid], S);
    }
}

// ---------------- per-graph offset Cg (+ zero g_acc), f-major coalesced W ----------
// Cg = be + fac*s1 + fac^3*t4
__global__ void k_cg(const float* __restrict__ be) {
    int idx = blockIdx.x * 256 + threadIdx.x;            // BB*MHs = 262144
    if (idx >= BB*MHs) return;
    g_acc[idx] = 0.f;
    int b = idx >> 11;
    int mh = idx & 2047;
    float fac = g_fact[b];
    const float* gs = g_gsum + b*24;
    float s1 = 0.f, t4 = 0.f;
    #pragma unroll
    for (int f = 0; f < 16; f++) {
        s1 += gs[f] * g_W14[f*MHs + mh];
        t4 += gs[f] * g_W14[(20+f)*MHs + mh];
    }
    #pragma unroll
    for (int j = 0; j < 4; j++) {
        s1 += gs[16+j] * g_W14[(16+j)*MHs + mh];   // de part of diag sums
        t4 += gs[20+j] * g_W14[(36+j)*MHs + mh];   // raw cols sums
    }
    g_Cg[idx] = be[mh] + fac*s1 + fac*fac*fac*t4;
}

// ---------------- mma.sync GEMM + ReLU + per-graph reduction (R11 epilogue) --------
// grid (16 mh-tiles, 391 node-tiles), 256 threads (8 warps, 4x2).
// D[128n x 128mh], K=48, single fp16: A16*W16.
__global__ __launch_bounds__(256, 2) void k_mm(const int* __restrict__ batch) {
    extern __shared__ char smem[];
    uint32_t sb = s2u(smem);
    int tid = threadIdx.x;
    int lane = tid & 31, warp = tid >> 5;
    int warpM = warp & 3, warpN = warp >> 2;
    int mb = blockIdx.x * 128, nb = blockIdx.y * 128;

    // ---- load 2 operand tiles into smem (row pitch 112B, 96B real) ----
    {
        int r = tid >> 1, half = tid & 1;
        const uint4* Ah = (const uint4*)(g_A16 + (size_t)(nb + r)*KK2) + half*3;
        const uint4* Wh = (const uint4*)(g_W16 + (size_t)(mb + r)*KK2) + half*3;
        char* base = smem + r*TPITCHB + half*48;
        #pragma unroll
        for (int i = 0; i < 3; i++) {
            *(uint4*)(base + SM_A + i*16) = Ah[i];
            *(uint4*)(base + SM_W + i*16) = Wh[i];
        }
    }
    __syncthreads();

    float c[2][8][4];
    #pragma unroll
    for (int i = 0; i < 2; i++)
        #pragma unroll
        for (int j = 0; j < 8; j++)
            #pragma unroll
            for (int q = 0; q < 4; q++) c[i][j][q] = 0.f;

    // ldmatrix per-lane address components
    int g8 = lane >> 3, l7 = lane & 7;
    int arow = ((g8 & 1) << 3) + l7;           // 0..15
    int aoff = (g8 >> 1) << 4;                 // 0 / 16 bytes
    int brow = ((g8 >> 1) << 3) + l7;
    int boff = (g8 & 1) << 4;
    uint32_t aA = sb + SM_A + (warpM*32 + arow)*TPITCHB + aoff;
    uint32_t bW = sb + SM_W + (warpN*64 + brow)*TPITCHB + boff;

    #pragma unroll
    for (int k = 0; k < 3; k++) {
        int kb = k * 32;                       // 16 k-elems = 32 bytes
        uint32_t a[2][4];
        #pragma unroll
        for (int i = 0; i < 2; i++)
            LDM4(a[i], aA + i*16*TPITCHB + kb);
        #pragma unroll
        for (int jj = 0; jj < 4; jj++) {
            uint32_t bh[4];
            LDM4(bh, bW + jj*16*TPITCHB + kb);
            #pragma unroll
            for (int i = 0; i < 2; i++) {
                mma16816(c[i][jj*2],   a[i], bh[0], bh[1]);
                mma16816(c[i][jj*2+1], a[i], bh[2], bh[3]);
            }
        }
    }
    __syncthreads();   // operand smem dead; reuse for epilogue

    // ---- epilogue: relu(C + Cg) -> buf, per-graph column sums ----
    int g0 = batch[nb];
    int nlast = nb + 127; if (nlast >= NN) nlast = NN - 1;
    int glast = batch[nlast];
    int*   flg = (int*)smem;                   // [128]
    float* cgs = (float*)(smem + 512);         // [2][128]
    float* buf = (float*)(smem + 2048);        // [128][BUFW]
    if (tid < 128) {
        int n = nb + tid;
        flg[tid] = (n < NN && batch[n] != g0) ? 1 : 0;
    } else {
        int t = tid - 128;
        cgs[t]       = g_Cg[(size_t)g0   *MHs + mb + t];
        cgs[128 + t] = g_Cg[(size_t)glast*MHs + mb + t];
    }
    __syncthreads();

    #pragma unroll
    for (int i = 0; i < 2; i++) {
        int ra = warpM*32 + i*16 + (lane >> 2);
        int rb = ra + 8;
        bool va = (nb + ra) < NN, vb = (nb + rb) < NN;
        const float* ca = cgs + flg[ra]*128;
        const float* cb = cgs + flg[rb]*128;
        #pragma unroll
        for (int j = 0; j < 8; j++) {
            int col = warpN*64 + j*8 + (lane & 3)*2;
            float2 v0, v1;
            v0.x = va ? fmaxf(c[i][j][0] + ca[col],   0.f) : 0.f;
            v0.y = va ? fmaxf(c[i][j][1] + ca[col+1], 0.f) : 0.f;
            v1.x = vb ? fmaxf(c[i][j][2] + cb[col],   0.f) : 0.f;
            v1.y = vb ? fmaxf(c[i][j][3] + cb[col+1], 0.f) : 0.f;
            *(float2*)(buf + (size_t)ra*BUFW + col) = v0;
            *(float2*)(buf + (size_t)rb*BUFW + col) = v1;
        }
    }
    __syncthreads();

    {
        int col = tid & 127, half = tid >> 7;
        float s0 = 0.f, s1 = 0.f;
        int r0 = half * 64;
        #pragma unroll 8
        for (int r = r0; r < r0 + 64; r++) {
            float v = buf[(size_t)r*BUFW + col];
            if (flg[r]) s1 += v; else s0 += v;
        }
        atomicAdd(&g_acc[(size_t)g0*MHs + mb + col], s0);
        if (glast != g0) atomicAdd(&g_acc[(size_t)glast*MHs + mb + col], s1);
    }
}

// ---------------- final (+ reset g_cnt for next replay) ----------------
__global__ void k_final(const float* __restrict__ be, const float* __restrict__ kinv,
                        float* __restrict__ out) {
    int b = blockIdx.x;
    int m = threadIdx.x;
    if (m == 0) g_cnt[b] = 0;
    float fac = g_fact[b];
    const float* acc = g_acc + (size_t)b*MHs + m*HHs;
    const float* beh = be + m*HHs;
    const float* kv  = kinv + m*HHs;
    float s = 0.f;
    #pragma unroll
    for (int h = 0; h < HHs; h++)
        s += (acc[h]*fac - fmaxf(beh[h], 0.f)) * kv[h];
    out[b*MMs + m] = s;
}

extern "C" void kernel_launch(void* const* d_in, const int* in_sizes, int n_in,
                              void* d_out, int out_size) {
    const float* x    = (const float*)d_in[0];
    const float* ea   = (const float*)d_in[1];
    const float* ke   = (const float*)d_in[2];
    const float* kinv = (const float*)d_in[3];
    const float* be   = (const float*)d_in[4];
    // d_in[5] = bias_inv: cancels in psi - zerograph
    const int* ei     = (const int*)d_in[6];
    const int* batch  = (const int*)d_in[7];
    float* out = (float*)d_out;

    cudaFuncSetAttribute(k_mm, cudaFuncAttributeMaxDynamicSharedMemorySize, SMEM_BYTES);

    k_init<<<1024, 256>>>(ke, batch);
    k_edge<<<(EE+255)/256, 256>>>(ei, ea);
    k_node<<<(NN+255)/256, 256>>>(x, ea, batch);
    k_cg<<<(BB*MHs)/256, 256>>>(be);
    dim3 gg(MHs/128, NTILES);
    k_mm<<<gg, 256, SMEM_BYTES>>>(batch);
    k_final<<<BB, MMs>>>(be, kinv, out);
}